// round 3
// baseline (speedup 1.0000x reference)
#include <cuda_runtime.h>
#include <math.h>

#define Bn 8
#define Cn 64
#define Hn 256
#define Wn 256
#define HWn (Hn*Wn)          // 65536
#define PIXELS (Bn*HWn)      // 524288

// Scratch for Q, K, V: 3 * 8*64*256*256 floats = 384 MiB (device global, no alloc)
__device__ float g_qkv[3ULL * Bn * Cn * Hn * Wn];

// ---------------------------------------------------------------------------
// Kernel 1: QKV projection.  Q/K/V[b,o,h,w] = sum_i W[o,i] * x[b,i,h,w] + b[o]
// One thread per pixel; 64 x-channels register-resident; weights in smem.
// ---------------------------------------------------------------------------
__global__ void qkv_kernel(const float* __restrict__ x,
                           const float* __restrict__ Wq, const float* __restrict__ bq,
                           const float* __restrict__ Wk, const float* __restrict__ bk,
                           const float* __restrict__ Wv, const float* __restrict__ bv)
{
    extern __shared__ float sm1[];
    float4* Wsm4 = (float4*)sm1;     // 192 outputs x 16 float4 (k) = 3072
    float*  bsm  = sm1 + 3072 * 4;   // 192

    const int tid = threadIdx.x;

    for (int idx = tid; idx < 192 * 16; idx += 256) {
        int o  = idx >> 4;
        int k4 = idx & 15;
        const float* src = (o < 64) ? Wq : ((o < 128) ? Wk : Wv);
        int oo = o & 63;
        Wsm4[idx] = reinterpret_cast<const float4*>(src + oo * 64)[k4];
    }
    if (tid < 192) {
        bsm[tid] = (tid < 64) ? bq[tid] : ((tid < 128) ? bk[tid - 64] : bv[tid - 128]);
    }
    __syncthreads();

    const int p  = blockIdx.x * 256 + tid;   // pixel id 0..524287
    const int b  = p >> 16;                  // / 65536
    const int hw = p & 65535;

    // Load 64 input channels into registers (coalesced: consecutive tid -> consecutive hw)
    float xv[64];
    const float* xp = x + (size_t)b * 64 * HWn + hw;
    #pragma unroll
    for (int i = 0; i < 64; i++) xv[i] = xp[(size_t)i * HWn];

    #pragma unroll 4
    for (int o = 0; o < 192; o++) {
        float acc0 = 0.f, acc1 = 0.f;
        #pragma unroll
        for (int k4 = 0; k4 < 16; k4 += 2) {
            float4 w0 = Wsm4[o * 16 + k4];
            float4 w1 = Wsm4[o * 16 + k4 + 1];
            acc0 += w0.x * xv[k4*4+0];
            acc0 += w0.y * xv[k4*4+1];
            acc0 += w0.z * xv[k4*4+2];
            acc0 += w0.w * xv[k4*4+3];
            acc1 += w1.x * xv[k4*4+4];
            acc1 += w1.y * xv[k4*4+5];
            acc1 += w1.z * xv[k4*4+6];
            acc1 += w1.w * xv[k4*4+7];
        }
        float acc = bsm[o] + acc0 + acc1;
        int proj = o >> 6;     // 0:Q 1:K 2:V
        int oo   = o & 63;
        g_qkv[((size_t)proj * Bn * Cn + (size_t)b * 64 + oo) * HWn + hw] = acc;
    }
}

// ---------------------------------------------------------------------------
// Kernel 2: per-(b,c) attention over rows + BN(eval) + PReLU, fused.
//   S[h,g] = sum_w Q[h,w]K[g,w] / 4 ;  P = softmax_g(S) ;  out[h,w]=sum_g P V[g,w]
// Block = one (b,c) slice, one 64-row h-tile. 256 threads as 16x16, 4x4 / 4x16
// register micro-tiles.
// Smem (floats): QV 16384 (QsT 256x64 in phase A, Vs 64x256 in phase C),
//                Ps 64x260 (padded), KsT 64x64, rowscale 64.
// ---------------------------------------------------------------------------
#define SMEM_ATTN_FLOATS (16384 + 64*260 + 64*64 + 64)

__global__ void attn_kernel(const float* __restrict__ gamma, const float* __restrict__ beta,
                            const float* __restrict__ rmean, const float* __restrict__ rvar,
                            const float* __restrict__ alphap, float* __restrict__ out)
{
    extern __shared__ float sm[];
    float* QV    = sm;                       // 16384
    float* Ps    = sm + 16384;               // 64 * 260
    float* KsT   = sm + 16384 + 64 * 260;    // 64 * 64
    float* rowsc = KsT + 64 * 64;            // 64

    const int tid = threadIdx.x;
    const int bc  = blockIdx.x >> 2;         // b*64 + c
    const int ht  = blockIdx.x & 3;
    const int c   = bc & 63;
    const int h0  = ht * 64;

    const float* Qg = g_qkv + (size_t)bc * HWn;
    const float* Kg = g_qkv + (size_t)(512 + bc) * HWn;
    const float* Vg = g_qkv + (size_t)(1024 + bc) * HWn;

    // ---- load Q tile transposed: QsT[w][h], stride 64 ----
    {
        int h = tid >> 2, wq = tid & 3;
        const float* qrow = Qg + (size_t)(h0 + h) * 256;
        #pragma unroll
        for (int w0 = 0; w0 < 256; w0 += 16) {
            int w = w0 + wq * 4;
            float4 v = *(const float4*)(qrow + w);
            QV[(w + 0) * 64 + h] = v.x;
            QV[(w + 1) * 64 + h] = v.y;
            QV[(w + 2) * 64 + h] = v.z;
            QV[(w + 3) * 64 + h] = v.w;
        }
    }

    const int ty = tid >> 4;   // 0..15 -> row group
    const int tx = tid & 15;   // 0..15 -> col group

    // ---- Phase A: S = Q K^T * 0.25 (scale = H^0.25 = 4) ----
    for (int gt = 0; gt < 4; gt++) {
        float acc[4][4] = {};
        for (int wt = 0; wt < 4; wt++) {
            __syncthreads();
            {   // load K tile transposed: KsT[w_local][g_local]
                int gl = tid >> 2, wq = tid & 3;
                const float* krow = Kg + (size_t)(gt * 64 + gl) * 256 + wt * 64 + wq * 16;
                #pragma unroll
                for (int i = 0; i < 4; i++) {
                    float4 v = *(const float4*)(krow + i * 4);
                    int w = wq * 16 + i * 4;
                    KsT[(w + 0) * 64 + gl] = v.x;
                    KsT[(w + 1) * 64 + gl] = v.y;
                    KsT[(w + 2) * 64 + gl] = v.z;
                    KsT[(w + 3) * 64 + gl] = v.w;
                }
            }
            __syncthreads();
            #pragma unroll 8
            for (int k = 0; k < 64; k++) {
                float4 a  = *(const float4*)(QV  + (wt * 64 + k) * 64 + ty * 4);
                float4 bb = *(const float4*)(KsT + k * 64 + tx * 4);
                acc[0][0] += a.x * bb.x; acc[0][1] += a.x * bb.y;
                acc[0][2] += a.x * bb.z; acc[0][3] += a.x * bb.w;
                acc[1][0] += a.y * bb.x; acc[1][1] += a.y * bb.y;
                acc[1][2] += a.y * bb.z; acc[1][3] += a.y * bb.w;
                acc[2][0] += a.z * bb.x; acc[2][1] += a.z * bb.y;
                acc[2][2] += a.z * bb.z; acc[2][3] += a.z * bb.w;
                acc[3][0] += a.w * bb.x; acc[3][1] += a.w * bb.y;
                acc[3][2] += a.w * bb.z; acc[3][3] += a.w * bb.w;
            }
        }
        #pragma unroll
        for (int i = 0; i < 4; i++) {
            float4 v = make_float4(acc[i][0] * 0.25f, acc[i][1] * 0.25f,
                                   acc[i][2] * 0.25f, acc[i][3] * 0.25f);
            *(float4*)(Ps + (ty * 4 + i) * 260 + gt * 64 + tx * 4) = v;
        }
    }
    __syncthreads();

    // ---- Phase B: softmax over g (store exp, fold 1/sum into epilogue) ----
    {
        int h = tid >> 2, q = tid & 3;
        float* prow = Ps + h * 260 + q * 64;
        float m = -1e30f;
        #pragma unroll 16
        for (int i = 0; i < 64; i++) m = fmaxf(m, prow[i]);
        m = fmaxf(m, __shfl_xor_sync(0xffffffffu, m, 1));
        m = fmaxf(m, __shfl_xor_sync(0xffffffffu, m, 2));
        float s = 0.f;
        #pragma unroll 16
        for (int i = 0; i < 64; i++) { float e = __expf(prow[i] - m); prow[i] = e; s += e; }
        s += __shfl_xor_sync(0xffffffffu, s, 1);
        s += __shfl_xor_sync(0xffffffffu, s, 2);
        if (q == 0) rowsc[h] = 1.0f / s;
    }

    // ---- Phase C: out = P * V (QV region reused for V tiles) ----
    float accc[4][16] = {};
    for (int kt = 0; kt < 4; kt++) {
        __syncthreads();
        {   // load V tile natural: Vs[g_local][w] stride 256 — FULL 256-wide rows
            int gl = tid >> 2, wq = tid & 3;
            const float* vrow = Vg + (size_t)(kt * 64 + gl) * 256;
            #pragma unroll
            for (int w0 = 0; w0 < 256; w0 += 64) {
                #pragma unroll
                for (int i = 0; i < 4; i++) {
                    int w = w0 + wq * 16 + i * 4;
                    *(float4*)(QV + gl * 256 + w) = *(const float4*)(vrow + w);
                }
            }
        }
        __syncthreads();
        #pragma unroll 8
        for (int k = 0; k < 64; k++) {
            int kk = kt * 64 + k;
            float a0 = Ps[(ty * 4 + 0) * 260 + kk];
            float a1 = Ps[(ty * 4 + 1) * 260 + kk];
            float a2 = Ps[(ty * 4 + 2) * 260 + kk];
            float a3 = Ps[(ty * 4 + 3) * 260 + kk];
            #pragma unroll
            for (int nt = 0; nt < 4; nt++) {
                float4 bb = *(const float4*)(QV + k * 256 + nt * 64 + tx * 4);
                accc[0][nt*4+0] += a0 * bb.x; accc[0][nt*4+1] += a0 * bb.y;
                accc[0][nt*4+2] += a0 * bb.z; accc[0][nt*4+3] += a0 * bb.w;
                accc[1][nt*4+0] += a1 * bb.x; accc[1][nt*4+1] += a1 * bb.y;
                accc[1][nt*4+2] += a1 * bb.z; accc[1][nt*4+3] += a1 * bb.w;
                accc[2][nt*4+0] += a2 * bb.x; accc[2][nt*4+1] += a2 * bb.y;
                accc[2][nt*4+2] += a2 * bb.z; accc[2][nt*4+3] += a2 * bb.w;
                accc[3][nt*4+0] += a3 * bb.x; accc[3][nt*4+1] += a3 * bb.y;
                accc[3][nt*4+2] += a3 * bb.z; accc[3][nt*4+3] += a3 * bb.w;
            }
        }
    }

    // ---- Epilogue: 1/sum, BN (eval), PReLU, store ----
    const float inv = gamma[c] * rsqrtf(rvar[c] + 1e-5f);
    const float sh  = beta[c] - rmean[c] * inv;
    const float al  = alphap[0];
    #pragma unroll
    for (int i = 0; i < 4; i++) {
        float rs = rowsc[ty * 4 + i];
        float* op = out + (size_t)bc * HWn + (size_t)(h0 + ty * 4 + i) * 256;
        #pragma unroll
        for (int nt = 0; nt < 4; nt++) {
            float4 v;
            v.x = accc[i][nt*4+0] * rs * inv + sh;
            v.y = accc[i][nt*4+1] * rs * inv + sh;
            v.z = accc[i][nt*4+2] * rs * inv + sh;
            v.w = accc[i][nt*4+3] * rs * inv + sh;
            v.x = (v.x >= 0.f) ? v.x : al * v.x;
            v.y = (v.y >= 0.f) ? v.y : al * v.y;
            v.z = (v.z >= 0.f) ? v.z : al * v.z;
            v.w = (v.w >= 0.f) ? v.w : al * v.w;
            *(float4*)(op + nt * 64 + tx * 4) = v;
        }
    }
}

// ---------------------------------------------------------------------------
extern "C" void kernel_launch(void* const* d_in, const int* in_sizes, int n_in,
                              void* d_out, int out_size)
{
    (void)in_sizes; (void)n_in; (void)out_size;
    const float* x     = (const float*)d_in[0];
    const float* Wq    = (const float*)d_in[1];
    const float* bq    = (const float*)d_in[2];
    const float* Wk    = (const float*)d_in[3];
    const float* bk    = (const float*)d_in[4];
    const float* Wv    = (const float*)d_in[5];
    const float* bv    = (const float*)d_in[6];
    const float* gamma = (const float*)d_in[7];
    const float* beta  = (const float*)d_in[8];
    const float* rmean = (const float*)d_in[9];
    const float* rvar  = (const float*)d_in[10];
    const float* alpha = (const float*)d_in[11];
    float* out = (float*)d_out;

    const int smem1 = (3072 * 4 + 192) * sizeof(float);          // 49,920 B
    const int smem2 = SMEM_ATTN_FLOATS * sizeof(float);          // 148,736 B
    cudaFuncSetAttribute(qkv_kernel,  cudaFuncAttributeMaxDynamicSharedMemorySize, smem1);
    cudaFuncSetAttribute(attn_kernel, cudaFuncAttributeMaxDynamicSharedMemorySize, smem2);

    qkv_kernel<<<PIXELS / 256, 256, smem1>>>(x, Wq, bq, Wk, bk, Wv, bv);
    attn_kernel<<<Bn * Cn * 4, 256, smem2>>>(gamma, beta, rmean, rvar, alpha, out);
}

// round 4
// speedup vs baseline: 1.1956x; 1.1956x over previous
#include <cuda_runtime.h>
#include <math.h>

#define Bn 8
#define Cn 64
#define Hn 256
#define Wn 256
#define HWn (Hn*Wn)          // 65536
#define PIXELS (Bn*HWn)      // 524288

typedef unsigned long long ull;

// Scratch for Q, K, V (device global, no alloc)
__device__ float g_qkv[3ULL * Bn * Cn * Hn * Wn];

// ---- f32x2 packed-FMA helpers (sm_103a; exact fp32 per half) ------------
__device__ __forceinline__ ull pk2(float lo, float hi) {
    ull r; asm("mov.b64 %0,{%1,%2};" : "=l"(r) : "f"(lo), "f"(hi)); return r;
}
__device__ __forceinline__ void upk2(ull v, float& lo, float& hi) {
    asm("mov.b64 {%0,%1},%2;" : "=f"(lo), "=f"(hi) : "l"(v));
}
__device__ __forceinline__ void ffma2(ull& d, ull a, ull b) {
    asm("fma.rn.f32x2 %0,%1,%2,%0;" : "+l"(d) : "l"(a), "l"(b));
}
// 16B shared load as two packed f32x2 operands
__device__ __forceinline__ void lds2(ull& a, ull& b, const float* p) {
    unsigned s = (unsigned)__cvta_generic_to_shared(p);
    asm volatile("ld.shared.v2.u64 {%0,%1},[%2];" : "=l"(a), "=l"(b) : "r"(s));
}

// ---------------------------------------------------------------------------
// Kernel 1: QKV projection with f32x2.  One thread per pixel.
// ---------------------------------------------------------------------------
__global__ __launch_bounds__(256, 2)
void qkv_kernel(const float* __restrict__ x,
                const float* __restrict__ Wq, const float* __restrict__ bq,
                const float* __restrict__ Wk, const float* __restrict__ bk,
                const float* __restrict__ Wv, const float* __restrict__ bv)
{
    extern __shared__ float sm1[];
    float* Wsm = sm1;                 // 192 x 64
    float* bsm = sm1 + 192 * 64;      // 192

    const int tid = threadIdx.x;

    for (int idx = tid; idx < 192 * 16; idx += 256) {
        int o  = idx >> 4;
        int k4 = idx & 15;
        const float* src = (o < 64) ? Wq : ((o < 128) ? Wk : Wv);
        int oo = o & 63;
        reinterpret_cast<float4*>(Wsm)[idx] =
            reinterpret_cast<const float4*>(src + oo * 64)[k4];
    }
    if (tid < 192) {
        bsm[tid] = (tid < 64) ? bq[tid] : ((tid < 128) ? bk[tid - 64] : bv[tid - 128]);
    }
    __syncthreads();

    const int p  = blockIdx.x * 256 + tid;
    const int b  = p >> 16;
    const int hw = p & 65535;

    // pack 64 input channels into 32 f32x2 pairs
    ull xp[32];
    const float* xpp = x + (size_t)b * 64 * HWn + hw;
    #pragma unroll
    for (int j = 0; j < 32; j++) {
        float a = xpp[(size_t)(2 * j) * HWn];
        float c = xpp[(size_t)(2 * j + 1) * HWn];
        xp[j] = pk2(a, c);
    }

    #pragma unroll 2
    for (int o = 0; o < 192; o++) {
        ull a0 = 0ull, a1 = 0ull;
        const float* wrow = Wsm + o * 64;
        #pragma unroll
        for (int k2 = 0; k2 < 16; k2++) {
            ull w0, w1;
            lds2(w0, w1, wrow + k2 * 4);
            ffma2(a0, w0, xp[k2 * 2]);
            ffma2(a1, w1, xp[k2 * 2 + 1]);
        }
        float l0, h0, l1, h1;
        upk2(a0, l0, h0); upk2(a1, l1, h1);
        float acc = bsm[o] + ((l0 + h0) + (l1 + h1));
        int proj = o >> 6;
        int oo   = o & 63;
        g_qkv[((size_t)proj * Bn * Cn + (size_t)b * 64 + oo) * HWn + hw] = acc;
    }
}

// ---------------------------------------------------------------------------
// Kernel 2: attention + BN + PReLU.  Block = one (b,c) x 64-row h-tile.
// Threads: 8x32 (ty2=warp 0..7 -> 8 h-rows each; tx2=lane 0..31 -> 8 cols each)
// 8x8 register micro-tile held as 8x4 packed f32x2 accumulators.
// Smem: PsT[256g][68] (P transposed, padded), union(QsT 32x64 + Ks 32x260 /
//       Vs 32x256 / red 512), rowsc[64].
// ---------------------------------------------------------------------------
#define STP 68
#define STK 260
#define PST_FLOATS (256 * STP)                       // 17408
#define UN_FLOATS  (32 * 64 + 32 * STK)              // 10368 (>= Vs 8192, red 512)
#define SMEM_ATTN_FLOATS (PST_FLOATS + UN_FLOATS + 64)

__global__ __launch_bounds__(256, 1)
void attn_kernel(const float* __restrict__ gamma, const float* __restrict__ beta,
                 const float* __restrict__ rmean, const float* __restrict__ rvar,
                 const float* __restrict__ alphap, float* __restrict__ out)
{
    extern __shared__ float sm[];
    float* PsT   = sm;                       // 256 x STP
    float* Un    = sm + PST_FLOATS;          // union region
    float* rowsc = sm + PST_FLOATS + UN_FLOATS;

    float* QsT = Un;                         // 32 x 64   (phase A)
    float* Ks  = Un + 32 * 64;               // 32 x STK  (phase A)
    float* Vs  = Un;                         // 32 x 256  (phase C)
    float* red = Un;                         // 512       (phase B)

    const int tid = threadIdx.x;
    const int ty2 = tid >> 5;                // 0..7
    const int tx2 = tid & 31;                // 0..31
    const int bc  = blockIdx.x >> 2;
    const int ht  = blockIdx.x & 3;
    const int c   = bc & 63;
    const int h0  = ht * 64;

    const float* Qg = g_qkv + (size_t)bc * HWn;
    const float* Kg = g_qkv + (size_t)(512 + bc) * HWn;
    const float* Vg = g_qkv + (size_t)(1024 + bc) * HWn;

    // ================= Phase A: S = Q K^T (64h x 256g), K dim = 256 w ======
    ull acc[8][4];
    #pragma unroll
    for (int i = 0; i < 8; i++)
        #pragma unroll
        for (int j = 0; j < 4; j++) acc[i][j] = 0ull;

    for (int ch = 0; ch < 8; ch++) {
        const int w0 = ch * 32;
        __syncthreads();
        {   // QsT[w_local][h] : 32 x 64
            int h = tid >> 2, wq = tid & 3;
            const float* qrow = Qg + (size_t)(h0 + h) * 256 + w0 + wq * 8;
            float4 v0 = *(const float4*)(qrow);
            float4 v1 = *(const float4*)(qrow + 4);
            int wb = wq * 8;
            QsT[(wb + 0) * 64 + h] = v0.x; QsT[(wb + 1) * 64 + h] = v0.y;
            QsT[(wb + 2) * 64 + h] = v0.z; QsT[(wb + 3) * 64 + h] = v0.w;
            QsT[(wb + 4) * 64 + h] = v1.x; QsT[(wb + 5) * 64 + h] = v1.y;
            QsT[(wb + 6) * 64 + h] = v1.z; QsT[(wb + 7) * 64 + h] = v1.w;
        }
        {   // Ks[w_local][g] : 32 x 256 (stride STK), transposed from gmem
            int g0 = (tid >> 3) * 8, wq = tid & 7;
            float4 r[8];
            #pragma unroll
            for (int r8 = 0; r8 < 8; r8++)
                r[r8] = *(const float4*)(Kg + (size_t)(g0 + r8) * 256 + w0 + wq * 4);
            const float* rf = (const float*)r;
            #pragma unroll
            for (int jj = 0; jj < 4; jj++) {
                float4 s0 = make_float4(rf[0 * 4 + jj], rf[1 * 4 + jj], rf[2 * 4 + jj], rf[3 * 4 + jj]);
                float4 s1 = make_float4(rf[4 * 4 + jj], rf[5 * 4 + jj], rf[6 * 4 + jj], rf[7 * 4 + jj]);
                *(float4*)(Ks + (wq * 4 + jj) * STK + g0)     = s0;
                *(float4*)(Ks + (wq * 4 + jj) * STK + g0 + 4) = s1;
            }
        }
        __syncthreads();
        #pragma unroll 4
        for (int k = 0; k < 32; k++) {
            float af[8];
            *(float4*)(af)     = *(const float4*)(QsT + k * 64 + ty2 * 8);
            *(float4*)(af + 4) = *(const float4*)(QsT + k * 64 + ty2 * 8 + 4);
            ull b0, b1, b2, b3;
            lds2(b0, b1, Ks + k * STK + tx2 * 8);
            lds2(b2, b3, Ks + k * STK + tx2 * 8 + 4);
            #pragma unroll
            for (int i = 0; i < 8; i++) {
                ull ad = pk2(af[i], af[i]);
                ffma2(acc[i][0], ad, b0); ffma2(acc[i][1], ad, b1);
                ffma2(acc[i][2], ad, b2); ffma2(acc[i][3], ad, b3);
            }
        }
    }

    // store S*0.25 transposed -> PsT[g][h]
    #pragma unroll
    for (int jp = 0; jp < 4; jp++) {
        float cl[8], dh[8];
        #pragma unroll
        for (int i = 0; i < 8; i++) upk2(acc[i][jp], cl[i], dh[i]);
        int g1 = tx2 * 8 + jp * 2;
        float* p1 = PsT + g1 * STP + ty2 * 8;
        float* p2 = PsT + (g1 + 1) * STP + ty2 * 8;
        *(float4*)(p1)     = make_float4(cl[0]*0.25f, cl[1]*0.25f, cl[2]*0.25f, cl[3]*0.25f);
        *(float4*)(p1 + 4) = make_float4(cl[4]*0.25f, cl[5]*0.25f, cl[6]*0.25f, cl[7]*0.25f);
        *(float4*)(p2)     = make_float4(dh[0]*0.25f, dh[1]*0.25f, dh[2]*0.25f, dh[3]*0.25f);
        *(float4*)(p2 + 4) = make_float4(dh[4]*0.25f, dh[5]*0.25f, dh[6]*0.25f, dh[7]*0.25f);
    }
    __syncthreads();

    // ================= Phase B: softmax over g (partial reduction) =========
    {
        const int h = tid & 63, q = tid >> 6;
        float m = -1e30f;
        #pragma unroll 8
        for (int i = 0; i < 64; i++) m = fmaxf(m, PsT[(q * 64 + i) * STP + h]);
        red[q * 64 + h] = m;
        __syncthreads();
        float M = fmaxf(fmaxf(red[h], red[64 + h]), fmaxf(red[128 + h], red[192 + h]));
        float s = 0.f;
        #pragma unroll 8
        for (int i = 0; i < 64; i++) {
            float* p = &PsT[(q * 64 + i) * STP + h];
            float e = __expf(*p - M);
            *p = e; s += e;
        }
        __syncthreads();       // all M reads done before red reuse
        red[256 + q * 64 + h] = s;
    }
    __syncthreads();
    if (tid < 64)
        rowsc[tid] = 1.f / (red[256 + tid] + red[320 + tid] + red[384 + tid] + red[448 + tid]);

    // ================= Phase C: out = P * V (64h x 256w), K dim = 256 g ====
    ull oacc[8][4];
    #pragma unroll
    for (int i = 0; i < 8; i++)
        #pragma unroll
        for (int j = 0; j < 4; j++) oacc[i][j] = 0ull;

    for (int ch = 0; ch < 8; ch++) {
        const int g0c = ch * 32;
        __syncthreads();
        {   // Vs[g_local][w] : 32 x 256, natural layout
            int gl = tid >> 3, wq = tid & 7;
            const float* vrow = Vg + (size_t)(g0c + gl) * 256;
            #pragma unroll
            for (int ii = 0; ii < 8; ii++) {
                int w = ii * 32 + wq * 4;
                *(float4*)(Vs + gl * 256 + w) = *(const float4*)(vrow + w);
            }
        }
        __syncthreads();
        #pragma unroll 4
        for (int k = 0; k < 32; k++) {
            float af[8];
            const float* prow = PsT + (g0c + k) * STP + ty2 * 8;
            *(float4*)(af)     = *(const float4*)(prow);
            *(float4*)(af + 4) = *(const float4*)(prow + 4);
            ull b0, b1, b2, b3;
            lds2(b0, b1, Vs + k * 256 + tx2 * 8);
            lds2(b2, b3, Vs + k * 256 + tx2 * 8 + 4);
            #pragma unroll
            for (int i = 0; i < 8; i++) {
                ull ad = pk2(af[i], af[i]);
                ffma2(oacc[i][0], ad, b0); ffma2(oacc[i][1], ad, b1);
                ffma2(oacc[i][2], ad, b2); ffma2(oacc[i][3], ad, b3);
            }
        }
    }

    // ================= Epilogue: 1/sum, BN(eval), PReLU, store =============
    const float inv = gamma[c] * rsqrtf(rvar[c] + 1e-5f);
    const float sh  = beta[c] - rmean[c] * inv;
    const float al  = alphap[0];
    #pragma unroll
    for (int i = 0; i < 8; i++) {
        float rs = rowsc[ty2 * 8 + i] * inv;
        float o[8];
        #pragma unroll
        for (int jp = 0; jp < 4; jp++) upk2(oacc[i][jp], o[2 * jp], o[2 * jp + 1]);
        #pragma unroll
        for (int j = 0; j < 8; j++) {
            float v = o[j] * rs + sh;
            o[j] = (v >= 0.f) ? v : al * v;
        }
        float* op = out + (size_t)bc * HWn + (size_t)(h0 + ty2 * 8 + i) * 256 + tx2 * 8;
        *(float4*)(op)     = make_float4(o[0], o[1], o[2], o[3]);
        *(float4*)(op + 4) = make_float4(o[4], o[5], o[6], o[7]);
    }
}

// ---------------------------------------------------------------------------
extern "C" void kernel_launch(void* const* d_in, const int* in_sizes, int n_in,
                              void* d_out, int out_size)
{
    (void)in_sizes; (void)n_in; (void)out_size;
    const float* x     = (const float*)d_in[0];
    const float* Wq    = (const float*)d_in[1];
    const float* bq    = (const float*)d_in[2];
    const float* Wk    = (const float*)d_in[3];
    const float* bk    = (const float*)d_in[4];
    const float* Wv    = (const float*)d_in[5];
    const float* bv    = (const float*)d_in[6];
    const float* gamma = (const float*)d_in[7];
    const float* beta  = (const float*)d_in[8];
    const float* rmean = (const float*)d_in[9];
    const float* rvar  = (const float*)d_in[10];
    const float* alpha = (const float*)d_in[11];
    float* out = (float*)d_out;

    const int smem1 = (192 * 64 + 192) * sizeof(float);
    const int smem2 = SMEM_ATTN_FLOATS * sizeof(float);   // 111,360 B
    cudaFuncSetAttribute(qkv_kernel,  cudaFuncAttributeMaxDynamicSharedMemorySize, smem1);
    cudaFuncSetAttribute(attn_kernel, cudaFuncAttributeMaxDynamicSharedMemorySize, smem2);

    qkv_kernel<<<PIXELS / 256, 256, smem1>>>(x, Wq, bq, Wk, bk, Wv, bv);
    attn_kernel<<<Bn * Cn * 4, 256, smem2>>>(gamma, beta, rmean, rvar, alpha, out);
}